// round 10
// baseline (speedup 1.0000x reference)
#include <cuda_runtime.h>
#include <stdint.h>

#define NEGF (-1e30f)

constexpr int T = 1024;
constexpr int B = 32;
constexpr int C = 96;
constexpr int W = 16;   // beam width
constexpr int P = 4;    // top paths
constexpr int S = 21;   // top lp columns kept per (b,t); staircase needs i <= 20

// per (b,t): top-S non-blank lp columns as packed keys (ord(lp)<<7 | (127-c)), desc
__device__ unsigned long long g_sorted[(size_t)B * T * S];

// ---------- key helpers ----------
__device__ __forceinline__ unsigned ford(float f) {
    unsigned u = __float_as_uint(f);
    return (u & 0x80000000u) ? ~u : (u | 0x80000000u);
}
__device__ __forceinline__ float funord(unsigned ord) {
    unsigned u = (ord & 0x80000000u) ? (ord ^ 0x80000000u) : ~ord;
    return __uint_as_float(u);
}
// larger score wins; ties -> lower global index wins (matches jax.lax.top_k)
__device__ __forceinline__ unsigned long long make_key(float f, int idx) {
    return ((unsigned long long)ford(f) << 11) | (unsigned long long)(2047 - idx);
}
__device__ __forceinline__ int key_idx(unsigned long long k) { return 2047 - (int)(k & 2047ULL); }
__device__ __forceinline__ float key_score(unsigned long long k) { return funord((unsigned)(k >> 11)); }

__device__ __forceinline__ float lae(float a, float b) {   // jnp.logaddexp
    float m = fmaxf(a, b);
    float d = fabsf(a - b);
    return m + log1pf(expf(-d));
}

// descending bitonic sort of 32 keys across a warp (lane = index)
__device__ __forceinline__ void sort32_desc(unsigned long long& v, int lane) {
    #pragma unroll
    for (int k2 = 2; k2 <= 32; k2 <<= 1) {
        #pragma unroll
        for (int j = k2 >> 1; j > 0; j >>= 1) {
            unsigned long long o = __shfl_xor_sync(0xffffffffu, v, j);
            bool takemax = ((lane & k2) == 0) == ((lane & j) == 0);
            bool bigger  = v > o;
            v = (takemax == bigger) ? v : o;
        }
    }
}

// top-16 (sorted desc, lanes 0-15) of two lists with top-16 sorted-desc in lanes 0-15
__device__ __forceinline__ unsigned long long merge_top16(
    unsigned long long a, unsigned long long b, int lane) {
    unsigned long long brev = __shfl_sync(0xffffffffu, b, (15 - lane) & 31);
    unsigned long long v = (a > brev) ? a : brev;
    #pragma unroll
    for (int j = 8; j > 0; j >>= 1) {
        unsigned long long o = __shfl_xor_sync(0xffffffffu, v, j);
        bool takemax = ((lane & j) == 0);
        bool bigger  = v > o;
        v = (takemax == bigger) ? v : o;
    }
    return v;   // lanes 0-15 valid
}

// ============================================================================
// Kernel 1: per-(b,t) bitonic sort of non-blank lp columns, keep top-S.
// ============================================================================
__global__ __launch_bounds__(256)
void presort_kernel(const float* __restrict__ data)   // [T, B, C]
{
    int warp = (blockIdx.x * blockDim.x + threadIdx.x) >> 5;
    if (warp >= B * T) return;
    int b = warp / T, t = warp - b * T;
    int lane = threadIdx.x & 31;

    const float* row = data + ((size_t)t * B + b) * C;
    unsigned long long k[4];
    #pragma unroll
    for (int r = 0; r < 4; ++r) {
        int c = r * 32 + lane;
        if (c >= 1 && c < C)
            k[r] = ((unsigned long long)ford(row[c]) << 7) | (unsigned long long)(127 - c);
        else
            k[r] = 0ULL;
    }
    #pragma unroll
    for (int k2 = 2; k2 <= 128; k2 <<= 1) {
        #pragma unroll
        for (int j = 64; j > 0; j >>= 1) {
            if (j >= k2) continue;
            if (j >= 32) {
                int rj = j >> 5;
                #pragma unroll
                for (int r = 0; r < 4; ++r) {
                    if ((r & rj) == 0) {
                        int pr = r | rj;
                        bool desc = (((r * 32) & k2) == 0);
                        unsigned long long a = k[r], c2 = k[pr];
                        unsigned long long mx = a > c2 ? a : c2;
                        unsigned long long mn = a > c2 ? c2 : a;
                        k[r]  = desc ? mx : mn;
                        k[pr] = desc ? mn : mx;
                    }
                }
            } else {
                #pragma unroll
                for (int r = 0; r < 4; ++r) {
                    unsigned long long o = __shfl_xor_sync(0xffffffffu, k[r], j);
                    int e = r * 32 + lane;
                    bool takemax = ((e & k2) == 0) == ((lane & j) == 0);
                    bool bigger  = k[r] > o;
                    k[r] = (takemax == bigger) ? k[r] : o;
                }
            }
        }
    }
    if (lane < S)
        g_sorted[((size_t)b * T + t) * S + lane] = k[0];
}

// ============================================================================
// Kernel 2: ONE WARP per batch element, fully register-resident, and the main
// loop is 100% branchless straight-line code (no divergent regions -> no
// BSSY/BSYNC, shuffle convergence provable -> no WARPSYNC).
// ============================================================================
__global__ __launch_bounds__(32, 1)
void ctc_beam_kernel(const float* __restrict__ data,      // [T, B, C]
                     const int*   __restrict__ data_len,  // [B]
                     float*       __restrict__ out)
{
    const int b    = blockIdx.x;
    const int lane = threadIdx.x;
    const int len  = data_len[b];
    const unsigned FULL = 0xffffffffu;

    __shared__ unsigned short s_bp[T + 1][W];   // row T = scrap for lanes 16-31
    __shared__ int   s_selslot[P], s_sellen[P];
    __shared__ float s_selscore[P];

    // static pool map: slot s = r*32+lane -> (w, i), staircase i <= 20/(w+1)
    // row counts {21,11,7,6,5,4,3,3,3,3,2,2,2,2,2,2} -> 78 cells; slots 78+ dead
    int pw[3], pi[3];
    {
        const int pref[17] = {0,21,32,39,45,50,54,57,60,63,66,68,70,72,74,76,78};
        #pragma unroll
        for (int r = 0; r < 3; ++r) {
            int s = r * 32 + lane;
            int w = -1, i = 0;
            #pragma unroll
            for (int ww = 0; ww < 16; ++ww)
                if (s >= pref[ww] && s < pref[ww + 1]) { w = ww; i = s - pref[ww]; }
            pw[r] = w; pi[r] = i;
        }
    }
    const int srt_lane = (lane < S) ? lane : (S - 1);   // clamped always-load index

    // row 0 into registers (lane l holds cols l, l+32, l+64; srt entry l)
    float lp0r, lp1r, lp2r;
    unsigned long long srt_cur;
    {
        const float* row0 = data + (size_t)b * C;
        lp0r = row0[lane]; lp1r = row0[32 + lane]; lp2r = row0[64 + lane];
        srt_cur = g_sorted[((size_t)b * T) * S + srt_lane];
    }

    // register beam state (lane = beam slot; high lanes carry garbage, never read)
    float pb   = (lane == 0) ? 0.0f : NEGF;
    float pnb  = NEGF;
    float ptot = lae(pb, pnb);
    int   llen = 0, llast = -1;

    #pragma unroll 2
    for (int t = 0; t < len; ++t) {
        // prefetch row min(t+1, T-1) unconditionally (branchless, all lanes)
        const int tp1 = (t + 1 < T) ? (t + 1) : (T - 1);
        const float* rown = data + (size_t)(tp1 * B + b) * C;
        float n0 = rown[lane], n1 = rown[32 + lane], n2 = rown[64 + lane];
        unsigned long long nsrt = g_sorted[((size_t)b * T + tp1) * S + srt_lane];

        // ---- stay / repeat candidates (lane = beam; pure shuffles, one lae)
        float lp_blank = __shfl_sync(FULL, lp0r, 0);
        int ix = (llen > 0) ? llast : 0;
        ix = (ix < 0) ? 0 : ((ix > 95) ? 0 : ix);          // garbage-lane safety
        float g0 = __shfl_sync(FULL, lp0r, ix);
        float g1 = __shfl_sync(FULL, lp1r, ix);
        float g2 = __shfl_sync(FULL, lp2r, ix);
        float lpl = (ix < 32) ? g0 : ((ix < 64) ? g1 : g2);
        float spb  = ptot + lp_blank;
        float spnb = (llen > 0) ? (pnb + lpl) : NEGF;
        unsigned long long staykey = make_key(lae(spb, spnb), lane);
        unsigned long long repkey  = (llen > 0)
            ? make_key(pb + lpl, W + lane * C + llast) : 0ULL;

        // ---- assemble pool: regs 0-2 = staircase ext cells, reg 3 = stay|rep
        unsigned long long k0, k1, k2, k3;
        {
            unsigned long long kk[3];
            #pragma unroll
            for (int r = 0; r < 3; ++r) {
                int w = pw[r];
                float pt = __shfl_sync(FULL, ptot,  w & 15);
                int   lw = __shfl_sync(FULL, llast, w & 15);
                unsigned long long e = __shfl_sync(FULL, srt_cur, pi[r]);
                int c = 127 - (int)(e & 127ULL);
                unsigned long long key =
                    make_key(funord((unsigned)(e >> 7)) + pt, W + w * C + c);
                kk[r] = (w >= 0 && c != lw) ? key : 0ULL;
            }
            k0 = kk[0]; k1 = kk[1]; k2 = kk[2];
            unsigned long long rk = __shfl_sync(FULL, repkey, lane & 15);
            k3 = (lane < W) ? staykey : rk;
        }

        // ---- exact top-16: 4x sort-32 (ILP) + 3 mirror merges
        sort32_desc(k0, lane);
        sort32_desc(k1, lane);
        sort32_desc(k2, lane);
        sort32_desc(k3, lane);
        unsigned long long m01 = merge_top16(k0, k1, lane);
        unsigned long long m23 = merge_top16(k2, k3, lane);
        unsigned long long fin = merge_top16(m01, m23, lane);   // lanes 0-15: rank-lane

        // ---- state update (all-register; high-lane garbage unread)
        int   idx   = key_idx(fin);
        float score = key_score(fin);
        bool  is_stay = idx < W;
        int   e2 = is_stay ? 0 : (idx - W);
        int   epar = e2 / C;
        int   csym = e2 - epar * C;
        int   parent = (is_stay ? idx : epar) & 15;
        float p_spb  = __shfl_sync(FULL, spb,   parent);
        float p_spnb = __shfl_sync(FULL, spnb,  parent);
        int   p_len  = __shfl_sync(FULL, llen,  parent);
        int   p_last = __shfl_sync(FULL, llast, parent);

        pb    = is_stay ? p_spb  : NEGF;
        pnb   = is_stay ? p_spnb : score;
        ptot  = score;
        llen  = is_stay ? p_len  : (p_len + 1);
        llast = is_stay ? p_last : csym;

        // unconditional backpointer store; lanes 16-31 -> scrap row T
        {
            int rowi = (lane < W) ? t : T;
            s_bp[rowi][lane & 15] =
                (unsigned short)((parent << 8) | (is_stay ? 0xFF : csym));
        }

        // rotate register buffers (warp-private, no sync)
        lp0r = n0; lp1r = n1; lp2r = n2; srt_cur = nsrt;
    }

    // ---- final top-P over total beam probabilities
    {
        unsigned long long key = (lane < W) ? make_key(ptot, lane) : 0ULL;
        #pragma unroll
        for (int r = 0; r < P; ++r) {
            unsigned long long v = key;
            #pragma unroll
            for (int o = 16; o; o >>= 1) {
                unsigned long long w2 = __shfl_xor_sync(FULL, v, o);
                v = (w2 > v) ? w2 : v;
            }
            if (key == v) key = 0ULL;
            int slot = key_idx(v) & 15;
            int sl = __shfl_sync(FULL, llen, slot);
            if (lane == 0) {
                s_selslot[r]  = slot;
                s_selscore[r] = key_score(v);
                s_sellen[r]   = sl;
            }
        }
    }
    __syncwarp();

    // ---- outputs (flattened float32): -scores, lens, labels
    float* o_neg = out;
    float* o_len = out + B * P;
    float* o_dec = out + 2 * B * P;

    if (lane < P) {
        o_neg[b * P + lane] = -s_selscore[lane];
        o_len[b * P + lane] = (float)s_sellen[lane];
    }
    for (int i = lane; i < P * T; i += 32)
        o_dec[(size_t)b * P * T + i] = -1.0f;
    __syncwarp();

    if (lane < P) {
        int slot = s_selslot[lane];
        int pos  = s_sellen[lane];
        float* dst = o_dec + ((size_t)b * P + lane) * T;
        for (int tt = len - 1; tt >= 0; --tt) {
            unsigned e = s_bp[tt][slot];
            int sym = e & 0xFF;
            slot    = e >> 8;
            if (sym != 0xFF) dst[--pos] = (float)sym;
        }
    }
}

extern "C" void kernel_launch(void* const* d_in, const int* in_sizes, int n_in,
                              void* d_out, int out_size) {
    const float* data = (const float*)d_in[0];
    const int*   dlen = (const int*)d_in[1];
    presort_kernel<<<(B * T + 7) / 8, 256>>>(data);
    ctc_beam_kernel<<<B, 32>>>(data, dlen, (float*)d_out);
}

// round 11
// speedup vs baseline: 1.3043x; 1.3043x over previous
#include <cuda_runtime.h>
#include <stdint.h>

#define NEGF (-1e30f)

constexpr int T = 1024;
constexpr int B = 32;
constexpr int C = 96;
constexpr int W = 16;   // beam width
constexpr int P = 4;    // top paths
constexpr int S = 21;   // top lp columns kept per (b,t); staircase needs i <= 20

// per (b,t): top-S non-blank lp columns as packed keys (ord(lp)<<7 | (127-c)), desc
__device__ unsigned long long g_sorted[(size_t)B * T * S];

// ---------- key helpers ----------
__device__ __forceinline__ unsigned ford(float f) {
    unsigned u = __float_as_uint(f);
    return (u & 0x80000000u) ? ~u : (u | 0x80000000u);
}
__device__ __forceinline__ float funord(unsigned ord) {
    unsigned u = (ord & 0x80000000u) ? (ord ^ 0x80000000u) : ~ord;
    return __uint_as_float(u);
}
// larger score wins; ties -> lower global index wins (matches jax.lax.top_k)
__device__ __forceinline__ unsigned long long make_key(float f, int idx) {
    return ((unsigned long long)ford(f) << 11) | (unsigned long long)(2047 - idx);
}
__device__ __forceinline__ int key_idx(unsigned long long k) { return 2047 - (int)(k & 2047ULL); }
__device__ __forceinline__ float key_score(unsigned long long k) { return funord((unsigned)(k >> 11)); }

__device__ __forceinline__ float lae(float a, float b) {   // jnp.logaddexp
    float m = fmaxf(a, b);
    float d = fabsf(a - b);
    return m + log1pf(expf(-d));
}

// descending bitonic sort of 32 keys across a warp (lane = index)
__device__ __forceinline__ void sort32_desc(unsigned long long& v, int lane) {
    #pragma unroll
    for (int k2 = 2; k2 <= 32; k2 <<= 1) {
        #pragma unroll
        for (int j = k2 >> 1; j > 0; j >>= 1) {
            unsigned long long o = __shfl_xor_sync(0xffffffffu, v, j);
            bool takemax = ((lane & k2) == 0) == ((lane & j) == 0);
            bool bigger  = v > o;
            v = (takemax == bigger) ? v : o;
        }
    }
}

// top-16 (sorted desc, lanes 0-15) of two lists with top-16 sorted-desc in lanes 0-15
__device__ __forceinline__ unsigned long long merge_top16(
    unsigned long long a, unsigned long long b, int lane) {
    unsigned long long brev = __shfl_sync(0xffffffffu, b, (15 - lane) & 31);
    unsigned long long v = (a > brev) ? a : brev;
    #pragma unroll
    for (int j = 8; j > 0; j >>= 1) {
        unsigned long long o = __shfl_xor_sync(0xffffffffu, v, j);
        bool takemax = ((lane & j) == 0);
        bool bigger  = v > o;
        v = (takemax == bigger) ? v : o;
    }
    return v;   // lanes 0-15 valid
}

// ============================================================================
// Kernel 1: per-(b,t) bitonic sort of non-blank lp columns, keep top-S.
// ============================================================================
__global__ __launch_bounds__(256)
void presort_kernel(const float* __restrict__ data)   // [T, B, C]
{
    int warp = (blockIdx.x * blockDim.x + threadIdx.x) >> 5;
    if (warp >= B * T) return;
    int b = warp / T, t = warp - b * T;
    int lane = threadIdx.x & 31;

    const float* row = data + ((size_t)t * B + b) * C;
    unsigned long long k[4];
    #pragma unroll
    for (int r = 0; r < 4; ++r) {
        int c = r * 32 + lane;
        if (c >= 1 && c < C)
            k[r] = ((unsigned long long)ford(row[c]) << 7) | (unsigned long long)(127 - c);
        else
            k[r] = 0ULL;
    }
    #pragma unroll
    for (int k2 = 2; k2 <= 128; k2 <<= 1) {
        #pragma unroll
        for (int j = 64; j > 0; j >>= 1) {
            if (j >= k2) continue;
            if (j >= 32) {
                int rj = j >> 5;
                #pragma unroll
                for (int r = 0; r < 4; ++r) {
                    if ((r & rj) == 0) {
                        int pr = r | rj;
                        bool desc = (((r * 32) & k2) == 0);
                        unsigned long long a = k[r], c2 = k[pr];
                        unsigned long long mx = a > c2 ? a : c2;
                        unsigned long long mn = a > c2 ? c2 : a;
                        k[r]  = desc ? mx : mn;
                        k[pr] = desc ? mn : mx;
                    }
                }
            } else {
                #pragma unroll
                for (int r = 0; r < 4; ++r) {
                    unsigned long long o = __shfl_xor_sync(0xffffffffu, k[r], j);
                    int e = r * 32 + lane;
                    bool takemax = ((e & k2) == 0) == ((lane & j) == 0);
                    bool bigger  = k[r] > o;
                    k[r] = (takemax == bigger) ? k[r] : o;
                }
            }
        }
    }
    if (lane < S)
        g_sorted[((size_t)b * T + t) * S + lane] = k[0];
}

// ============================================================================
// Kernel 2: 4 WARPS per batch element — pool reg k lives in warp k (4 SMSPs
// share the sort work). Beam state replicated in every warp's registers and
// updated identically (bit-exact), so ONE barrier per step suffices with a
// double-buffered s_top. Selection math identical to the proven R8 kernel.
// ============================================================================
__global__ __launch_bounds__(128, 1)
void ctc_beam_kernel(const float* __restrict__ data,      // [T, B, C]
                     const int*   __restrict__ data_len,  // [B]
                     float*       __restrict__ out)
{
    const int b    = blockIdx.x;
    const int tid  = threadIdx.x;
    const int lane = tid & 31;
    const int wid  = tid >> 5;
    const int len  = data_len[b];
    const unsigned FULL = 0xffffffffu;

    __shared__ unsigned long long s_top[2][4][W];   // [parity][warp][rank]
    __shared__ unsigned short s_bp[T][W];           // (parent<<8)|sym, 0xFF = stay
    __shared__ int   s_selslot[P], s_sellen[P];
    __shared__ float s_selscore[P];

    // staircase map for warps 0-2: slot s = wid*32+lane -> (w, i), i <= 20/(w+1)
    // row counts {21,11,7,6,5,4,3,3,3,3,2,2,2,2,2,2} -> 78 cells; slots 78+ dead
    int pw = -1, pi = 0;
    if (wid < 3) {
        const int pref[17] = {0,21,32,39,45,50,54,57,60,63,66,68,70,72,74,76,78};
        int s = wid * 32 + lane;
        #pragma unroll
        for (int ww = 0; ww < 16; ++ww)
            if (s >= pref[ww] && s < pref[ww + 1]) { pw = ww; pi = s - pref[ww]; }
    }

    // row 0 into registers (per warp; lane l holds cols l, l+32, l+64)
    float lp0r, lp1r, lp2r;
    unsigned long long srt_cur = 0ULL;
    {
        const float* row0 = data + (size_t)b * C;
        lp0r = row0[lane]; lp1r = row0[32 + lane]; lp2r = row0[64 + lane];
        if (lane < S) srt_cur = g_sorted[((size_t)b * T) * S + lane];
    }

    // replicated register beam state (lane = beam slot; high lanes never read)
    float pb   = (lane == 0) ? 0.0f : NEGF;
    float pnb  = NEGF;
    float ptot = lae(pb, pnb);
    int   llen = 0, llast = -1;

    for (int t = 0; t < len; ++t) {
        // prefetch row t+1 (per warp; consumed at rotation below)
        float n0 = 0.f, n1 = 0.f, n2 = 0.f; unsigned long long nsrt = 0ULL;
        if (t + 1 < T) {
            const float* rown = data + (size_t)((t + 1) * B + b) * C;
            n0 = rown[lane]; n1 = rown[32 + lane]; n2 = rown[64 + lane];
            if (lane < S) nsrt = g_sorted[((size_t)b * T + t + 1) * S + lane];
        }

        // ---- stay/rep probabilities (every warp: needed for the state update)
        float lp_blank = __shfl_sync(FULL, lp0r, 0);
        int ix = (llen > 0) ? llast : 0;
        ix = (ix < 0) ? 0 : ((ix > 95) ? 0 : ix);
        float g0 = __shfl_sync(FULL, lp0r, ix);
        float g1 = __shfl_sync(FULL, lp1r, ix);
        float g2 = __shfl_sync(FULL, lp2r, ix);
        float lpl = (ix < 32) ? g0 : ((ix < 64) ? g1 : g2);
        float spb  = ptot + lp_blank;
        float spnb = (llen > 0) ? (pnb + lpl) : NEGF;

        // ---- pool build: warps 0-2 = staircase ext cells; warp 3 = stay|rep
        unsigned long long k;
        if (wid == 3) {
            unsigned long long staykey = make_key(lae(spb, spnb), lane);
            unsigned long long repkey  = (llen > 0)
                ? make_key(pb + lpl, W + lane * C + llast) : 0ULL;
            unsigned long long rk = __shfl_sync(FULL, repkey, lane & 15);
            k = (lane < W) ? staykey : rk;
        } else {
            float pt = __shfl_sync(FULL, ptot,  pw & 15);
            int   lw = __shfl_sync(FULL, llast, pw & 15);
            unsigned long long e = __shfl_sync(FULL, srt_cur, pi);
            int c = 127 - (int)(e & 127ULL);
            unsigned long long key =
                make_key(funord((unsigned)(e >> 7)) + pt, W + pw * C + c);
            k = (pw >= 0 && c != lw) ? key : 0ULL;
        }

        // ---- each warp sorts its own 32 candidates (4 SMSPs in parallel)
        sort32_desc(k, lane);
        if (lane < W) s_top[t & 1][wid][lane] = k;
        __syncthreads();                              // the ONE barrier per step

        // ---- every warp: identical 2-level merge + state update (redundant)
        unsigned long long l0 = s_top[t & 1][0][lane & 15];
        unsigned long long l1 = s_top[t & 1][1][lane & 15];
        unsigned long long l2 = s_top[t & 1][2][lane & 15];
        unsigned long long l3 = s_top[t & 1][3][lane & 15];
        unsigned long long m01 = merge_top16(l0, l1, lane);
        unsigned long long m23 = merge_top16(l2, l3, lane);
        unsigned long long fin = merge_top16(m01, m23, lane); // lanes 0-15: rank-lane

        int   idx   = key_idx(fin);
        float score = key_score(fin);
        bool  is_stay = idx < W;
        int   e2 = is_stay ? 0 : (idx - W);
        int   epar = e2 / C;
        int   csym = e2 - epar * C;
        int   parent = (is_stay ? idx : epar) & 15;
        float p_spb  = __shfl_sync(FULL, spb,   parent);
        float p_spnb = __shfl_sync(FULL, spnb,  parent);
        int   p_len  = __shfl_sync(FULL, llen,  parent);
        int   p_last = __shfl_sync(FULL, llast, parent);

        pb    = is_stay ? p_spb  : NEGF;
        pnb   = is_stay ? p_spnb : score;
        ptot  = score;
        llen  = is_stay ? p_len  : (p_len + 1);
        llast = is_stay ? p_last : csym;

        if (wid == 0 && lane < W)
            s_bp[t][lane] = (unsigned short)((parent << 8) | (is_stay ? 0xFF : csym));

        // rotate register buffers (warp-private)
        lp0r = n0; lp1r = n1; lp2r = n2; srt_cur = nsrt;
    }

    // ---- final top-P over total beam probabilities (warp 0)
    if (wid == 0) {
        unsigned long long key = (lane < W) ? make_key(ptot, lane) : 0ULL;
        #pragma unroll
        for (int r = 0; r < P; ++r) {
            unsigned long long v = key;
            #pragma unroll
            for (int o = 16; o; o >>= 1) {
                unsigned long long w2 = __shfl_xor_sync(FULL, v, o);
                v = (w2 > v) ? w2 : v;
            }
            if (key == v) key = 0ULL;
            int slot = key_idx(v) & 15;
            int sl = __shfl_sync(FULL, llen, slot);
            if (lane == 0) {
                s_selslot[r]  = slot;
                s_selscore[r] = key_score(v);
                s_sellen[r]   = sl;
            }
        }
    }
    __syncthreads();

    // ---- outputs (flattened float32): -scores, lens, labels
    float* o_neg = out;
    float* o_len = out + B * P;
    float* o_dec = out + 2 * B * P;

    if (tid < P) {
        o_neg[b * P + tid] = -s_selscore[tid];
        o_len[b * P + tid] = (float)s_sellen[tid];
    }
    for (int i = tid; i < P * T; i += 128)
        o_dec[(size_t)b * P * T + i] = -1.0f;
    __syncthreads();

    if (tid < P) {
        int slot = s_selslot[tid];
        int pos  = s_sellen[tid];
        float* dst = o_dec + ((size_t)b * P + tid) * T;
        for (int tt = len - 1; tt >= 0; --tt) {
            unsigned e = s_bp[tt][slot];
            int sym = e & 0xFF;
            slot    = e >> 8;
            if (sym != 0xFF) dst[--pos] = (float)sym;
        }
    }
}

extern "C" void kernel_launch(void* const* d_in, const int* in_sizes, int n_in,
                              void* d_out, int out_size) {
    const float* data = (const float*)d_in[0];
    const int*   dlen = (const int*)d_in[1];
    presort_kernel<<<(B * T + 7) / 8, 256>>>(data);
    ctc_beam_kernel<<<B, 128>>>(data, dlen, (float*)d_out);
}

// round 12
// speedup vs baseline: 1.6199x; 1.2419x over previous
#include <cuda_runtime.h>
#include <stdint.h>

#define NEGF (-1e30f)

constexpr int T = 1024;
constexpr int B = 32;
constexpr int C = 96;
constexpr int W = 16;   // beam width
constexpr int P = 4;    // top paths
constexpr int S = 21;   // top lp columns kept per (b,t); staircase needs i <= 20

// per (b,t): top-S non-blank lp columns as packed keys (ord(lp)<<7 | (127-c)), desc
__device__ unsigned long long g_sorted[(size_t)B * T * S];

// ---------- key helpers ----------
__device__ __forceinline__ unsigned ford(float f) {
    unsigned u = __float_as_uint(f);
    return (u & 0x80000000u) ? ~u : (u | 0x80000000u);
}
__device__ __forceinline__ float funord(unsigned ord) {
    unsigned u = (ord & 0x80000000u) ? (ord ^ 0x80000000u) : ~ord;
    return __uint_as_float(u);
}
// larger score wins; ties -> lower global index wins (matches jax.lax.top_k)
__device__ __forceinline__ unsigned long long make_key(float f, int idx) {
    return ((unsigned long long)ford(f) << 11) | (unsigned long long)(2047 - idx);
}
__device__ __forceinline__ int key_idx(unsigned long long k) { return 2047 - (int)(k & 2047ULL); }
__device__ __forceinline__ float key_score(unsigned long long k) { return funord((unsigned)(k >> 11)); }

__device__ __forceinline__ float lae(float a, float b) {   // jnp.logaddexp
    float m = fmaxf(a, b);
    float d = fabsf(a - b);
    return m + log1pf(expf(-d));
}

// descending bitonic sort of 32 keys across a warp (lane = index)
__device__ __forceinline__ void sort32_desc(unsigned long long& v, int lane) {
    #pragma unroll
    for (int k2 = 2; k2 <= 32; k2 <<= 1) {
        #pragma unroll
        for (int j = k2 >> 1; j > 0; j >>= 1) {
            unsigned long long o = __shfl_xor_sync(0xffffffffu, v, j);
            bool takemax = ((lane & k2) == 0) == ((lane & j) == 0);
            bool bigger  = v > o;
            v = (takemax == bigger) ? v : o;
        }
    }
}

// ============================================================================
// Kernel 1: per-(b,t) bitonic sort of non-blank lp columns, keep top-S.
// ============================================================================
__global__ __launch_bounds__(256)
void presort_kernel(const float* __restrict__ data)   // [T, B, C]
{
    int warp = (blockIdx.x * blockDim.x + threadIdx.x) >> 5;
    if (warp >= B * T) return;
    int b = warp / T, t = warp - b * T;
    int lane = threadIdx.x & 31;

    const float* row = data + ((size_t)t * B + b) * C;
    unsigned long long k[4];
    #pragma unroll
    for (int r = 0; r < 4; ++r) {
        int c = r * 32 + lane;
        if (c >= 1 && c < C)
            k[r] = ((unsigned long long)ford(row[c]) << 7) | (unsigned long long)(127 - c);
        else
            k[r] = 0ULL;
    }
    #pragma unroll
    for (int k2 = 2; k2 <= 128; k2 <<= 1) {
        #pragma unroll
        for (int j = 64; j > 0; j >>= 1) {
            if (j >= k2) continue;
            if (j >= 32) {
                int rj = j >> 5;
                #pragma unroll
                for (int r = 0; r < 4; ++r) {
                    if ((r & rj) == 0) {
                        int pr = r | rj;
                        bool desc = (((r * 32) & k2) == 0);
                        unsigned long long a = k[r], c2 = k[pr];
                        unsigned long long mx = a > c2 ? a : c2;
                        unsigned long long mn = a > c2 ? c2 : a;
                        k[r]  = desc ? mx : mn;
                        k[pr] = desc ? mn : mx;
                    }
                }
            } else {
                #pragma unroll
                for (int r = 0; r < 4; ++r) {
                    unsigned long long o = __shfl_xor_sync(0xffffffffu, k[r], j);
                    int e = r * 32 + lane;
                    bool takemax = ((e & k2) == 0) == ((lane & j) == 0);
                    bool bigger  = k[r] > o;
                    k[r] = (takemax == bigger) ? k[r] : o;
                }
            }
        }
    }
    if (lane < S)
        g_sorted[((size_t)b * T + t) * S + lane] = k[0];
}

// ============================================================================
// Kernel 2: 4 warps per batch element, pool reg k in warp k, ONE barrier/step.
// NEW: packed dual-merge (m01 in lanes 0-15 while m23 in 16-31 -> 10 strict
// passes, 2 LDS) and fully branchless loop edges (no BSSY/BSYNC skew).
// ============================================================================
__global__ __launch_bounds__(128, 1)
void ctc_beam_kernel(const float* __restrict__ data,      // [T, B, C]
                     const int*   __restrict__ data_len,  // [B]
                     float*       __restrict__ out)
{
    const int b    = blockIdx.x;
    const int tid  = threadIdx.x;
    const int lane = tid & 31;
    const int wid  = tid >> 5;
    const int len  = data_len[b];
    const unsigned FULL = 0xffffffffu;

    __shared__ unsigned long long s_top[2][4][32];  // [parity][warp][lane] (full 32)
    __shared__ unsigned short s_bp[T + 1][W];       // row T = scrap (never read)
    __shared__ int   s_selslot[P], s_sellen[P];
    __shared__ float s_selscore[P];

    // staircase map for warps 0-2: slot s = wid*32+lane -> (w, i), i <= 20/(w+1)
    // row counts {21,11,7,6,5,4,3,3,3,3,2,2,2,2,2,2} -> 78 cells; slots 78+ dead
    int pw = -1, pi = 0;
    if (wid < 3) {
        const int pref[17] = {0,21,32,39,45,50,54,57,60,63,66,68,70,72,74,76,78};
        int s = wid * 32 + lane;
        #pragma unroll
        for (int ww = 0; ww < 16; ++ww)
            if (s >= pref[ww] && s < pref[ww + 1]) { pw = ww; pi = s - pref[ww]; }
    }
    const int srt_lane = (lane < S) ? lane : (S - 1);   // clamped always-load

    // row 0 into registers (per warp; lane l holds cols l, l+32, l+64)
    float lp0r, lp1r, lp2r;
    unsigned long long srt_cur;
    {
        const float* row0 = data + (size_t)b * C;
        lp0r = row0[lane]; lp1r = row0[32 + lane]; lp2r = row0[64 + lane];
        srt_cur = g_sorted[((size_t)b * T) * S + srt_lane];
    }

    // replicated register beam state (lane = beam slot; high lanes never read)
    float pb   = (lane == 0) ? 0.0f : NEGF;
    float pnb  = NEGF;
    float ptot = lae(pb, pnb);
    int   llen = 0, llast = -1;

    for (int t = 0; t < len; ++t) {
        // branchless prefetch of row min(t+1, T-1)
        const int tp1 = (t + 1 < T) ? (t + 1) : (T - 1);
        const float* rown = data + (size_t)(tp1 * B + b) * C;
        float n0 = rown[lane], n1 = rown[32 + lane], n2 = rown[64 + lane];
        unsigned long long nsrt = g_sorted[((size_t)b * T + tp1) * S + srt_lane];

        // ---- stay/rep probabilities (every warp; needed for state update)
        float lp_blank = __shfl_sync(FULL, lp0r, 0);
        int ix = (llen > 0) ? llast : 0;
        ix = (ix < 0) ? 0 : ((ix > 95) ? 0 : ix);
        float g0 = __shfl_sync(FULL, lp0r, ix);
        float g1 = __shfl_sync(FULL, lp1r, ix);
        float g2 = __shfl_sync(FULL, lp2r, ix);
        float lpl = (ix < 32) ? g0 : ((ix < 64) ? g1 : g2);
        float spb  = ptot + lp_blank;
        float spnb = (llen > 0) ? (pnb + lpl) : NEGF;

        // ---- pool build: warps 0-2 = staircase ext cells; warp 3 = stay|rep
        unsigned long long k;
        if (wid == 3) {
            unsigned long long staykey = make_key(lae(spb, spnb), lane);
            unsigned long long repkey  = (llen > 0)
                ? make_key(pb + lpl, W + lane * C + llast) : 0ULL;
            unsigned long long rk = __shfl_sync(FULL, repkey, lane & 15);
            k = (lane < W) ? staykey : rk;
        } else {
            float pt = __shfl_sync(FULL, ptot,  pw & 15);
            int   lw = __shfl_sync(FULL, llast, pw & 15);
            unsigned long long e = __shfl_sync(FULL, srt_cur, pi);
            int c = 127 - (int)(e & 127ULL);
            unsigned long long key =
                make_key(funord((unsigned)(e >> 7)) + pt, W + pw * C + c);
            k = (pw >= 0 && c != lw) ? key : 0ULL;
        }

        // ---- each warp sorts its own 32 candidates (4 SMSPs in parallel)
        sort32_desc(k, lane);
        s_top[t & 1][wid][lane] = k;        // all 32 lanes: no divergence
        __syncthreads();                    // the ONE barrier per step

        // ---- packed dual-merge: lanes 0-15 do lists(0,1), 16-31 do (2,3)
        const int half2 = (lane >> 4) << 1;               // 0 or 2
        unsigned long long a = s_top[t & 1][half2][lane & 15];
        unsigned long long bq = s_top[t & 1][half2 + 1][lane & 15];
        unsigned long long bm = __shfl_xor_sync(FULL, bq, 15);   // mirror in-half
        unsigned long long v = (a > bm) ? a : bm;
        #pragma unroll
        for (int j = 8; j > 0; j >>= 1) {                 // clean within halves
            unsigned long long o = __shfl_xor_sync(FULL, v, j);
            bool takemax = ((lane & j) == 0);
            bool bigger  = v > o;
            v = (takemax == bigger) ? v : o;
        }
        // final merge: m01 (lanes 0-15) vs m23 (lanes 16-31), mirror = lane^31
        unsigned long long bm2 = __shfl_xor_sync(FULL, v, 31);
        unsigned long long f = (v > bm2) ? v : bm2;
        #pragma unroll
        for (int j = 8; j > 0; j >>= 1) {
            unsigned long long o = __shfl_xor_sync(FULL, f, j);
            bool takemax = ((lane & j) == 0);
            bool bigger  = f > o;
            f = (takemax == bigger) ? f : o;
        }
        // f: lanes 0-15 hold rank-lane winner (lanes 16-31 garbage, never read)

        // ---- state update (replicated, bit-identical in every warp)
        int   idx   = key_idx(f);
        float score = key_score(f);
        bool  is_stay = idx < W;
        int   e2 = is_stay ? 0 : (idx - W);
        int   epar = e2 / C;
        int   csym = e2 - epar * C;
        int   parent = (is_stay ? idx : epar) & 15;
        float p_spb  = __shfl_sync(FULL, spb,   parent);
        float p_spnb = __shfl_sync(FULL, spnb,  parent);
        int   p_len  = __shfl_sync(FULL, llen,  parent);
        int   p_last = __shfl_sync(FULL, llast, parent);

        pb    = is_stay ? p_spb  : NEGF;
        pnb   = is_stay ? p_spnb : score;
        ptot  = score;
        llen  = is_stay ? p_len  : (p_len + 1);
        llast = is_stay ? p_last : csym;

        // branchless backpointer store: warp0 lanes 0-15 -> row t, rest -> scrap
        {
            int rowi = (wid == 0 && lane < W) ? t : T;
            s_bp[rowi][lane & 15] =
                (unsigned short)((parent << 8) | (is_stay ? 0xFF : csym));
        }

        // rotate register buffers (warp-private)
        lp0r = n0; lp1r = n1; lp2r = n2; srt_cur = nsrt;
    }

    // ---- final top-P over total beam probabilities (warp 0)
    if (wid == 0) {
        unsigned long long key = (lane < W) ? make_key(ptot, lane) : 0ULL;
        #pragma unroll
        for (int r = 0; r < P; ++r) {
            unsigned long long v = key;
            #pragma unroll
            for (int o = 16; o; o >>= 1) {
                unsigned long long w2 = __shfl_xor_sync(FULL, v, o);
                v = (w2 > v) ? w2 : v;
            }
            if (key == v) key = 0ULL;
            int slot = key_idx(v) & 15;
            int sl = __shfl_sync(FULL, llen, slot);
            if (lane == 0) {
                s_selslot[r]  = slot;
                s_selscore[r] = key_score(v);
                s_sellen[r]   = sl;
            }
        }
    }
    __syncthreads();

    // ---- outputs (flattened float32): -scores, lens, labels
    float* o_neg = out;
    float* o_len = out + B * P;
    float* o_dec = out + 2 * B * P;

    if (tid < P) {
        o_neg[b * P + tid] = -s_selscore[tid];
        o_len[b * P + tid] = (float)s_sellen[tid];
    }
    for (int i = tid; i < P * T; i += 128)
        o_dec[(size_t)b * P * T + i] = -1.0f;
    __syncthreads();

    if (tid < P) {
        int slot = s_selslot[tid];
        int pos  = s_sellen[tid];
        float* dst = o_dec + ((size_t)b * P + tid) * T;
        for (int tt = len - 1; tt >= 0; --tt) {
            unsigned e = s_bp[tt][slot];
            int sym = e & 0xFF;
            slot    = e >> 8;
            if (sym != 0xFF) dst[--pos] = (float)sym;
        }
    }
}

extern "C" void kernel_launch(void* const* d_in, const int* in_sizes, int n_in,
                              void* d_out, int out_size) {
    const float* data = (const float*)d_in[0];
    const int*   dlen = (const int*)d_in[1];
    presort_kernel<<<(B * T + 7) / 8, 256>>>(data);
    ctc_beam_kernel<<<B, 128>>>(data, dlen, (float*)d_out);
}

// round 13
// speedup vs baseline: 1.6550x; 1.0217x over previous
#include <cuda_runtime.h>
#include <stdint.h>

#define NEGF (-1e30f)

constexpr int T = 1024;
constexpr int B = 32;
constexpr int C = 96;
constexpr int W = 16;   // beam width
constexpr int P = 4;    // top paths
constexpr int S = 21;   // top lp columns kept per (b,t); staircase needs i <= 20

// per (b,t): top-S non-blank lp columns as packed keys (ord(lp)<<7 | (127-c)), desc
__device__ unsigned long long g_sorted[(size_t)B * T * S];

// ---------- key helpers ----------
__device__ __forceinline__ unsigned ford(float f) {
    unsigned u = __float_as_uint(f);
    return (u & 0x80000000u) ? ~u : (u | 0x80000000u);
}
__device__ __forceinline__ float funord(unsigned ord) {
    unsigned u = (ord & 0x80000000u) ? (ord ^ 0x80000000u) : ~ord;
    return __uint_as_float(u);
}
// Payload-packed key: [54:23]=ord(score) [22:12]=2047-idx [11]=is_stay
// [10:7]=parent [6:0]=csym.  Order: higher score wins; ties -> lower idx wins
// (matches jax.lax.top_k). Payload bits only compared when (ord,idx) equal,
// which cannot happen for distinct candidates.
__device__ __forceinline__ unsigned long long pack_key(
    float f, int idx, int is_stay, int parent, int csym) {
    return ((unsigned long long)ford(f) << 23)
         | ((unsigned long long)(2047 - idx) << 12)
         | ((unsigned long long)is_stay << 11)
         | ((unsigned long long)parent << 7)
         | (unsigned long long)csym;
}
__device__ __forceinline__ float key_score(unsigned long long k) {
    return funord((unsigned)(k >> 23));
}

__device__ __forceinline__ float lae(float a, float b) {   // jnp.logaddexp
    float m = fmaxf(a, b);
    float d = fabsf(a - b);
    return m + log1pf(expf(-d));
}

// descending bitonic sort of 32 keys across a warp (lane = index)
__device__ __forceinline__ void sort32_desc(unsigned long long& v, int lane) {
    #pragma unroll
    for (int k2 = 2; k2 <= 32; k2 <<= 1) {
        #pragma unroll
        for (int j = k2 >> 1; j > 0; j >>= 1) {
            unsigned long long o = __shfl_xor_sync(0xffffffffu, v, j);
            bool takemax = ((lane & k2) == 0) == ((lane & j) == 0);
            bool bigger  = v > o;
            v = (takemax == bigger) ? v : o;
        }
    }
}

// ============================================================================
// Kernel 1: per-(b,t) bitonic sort of non-blank lp columns, keep top-S.
// ============================================================================
__global__ __launch_bounds__(256)
void presort_kernel(const float* __restrict__ data)   // [T, B, C]
{
    int warp = (blockIdx.x * blockDim.x + threadIdx.x) >> 5;
    if (warp >= B * T) return;
    int b = warp / T, t = warp - b * T;
    int lane = threadIdx.x & 31;

    const float* row = data + ((size_t)t * B + b) * C;
    unsigned long long k[4];
    #pragma unroll
    for (int r = 0; r < 4; ++r) {
        int c = r * 32 + lane;
        if (c >= 1 && c < C)
            k[r] = ((unsigned long long)ford(row[c]) << 7) | (unsigned long long)(127 - c);
        else
            k[r] = 0ULL;
    }
    #pragma unroll
    for (int k2 = 2; k2 <= 128; k2 <<= 1) {
        #pragma unroll
        for (int j = 64; j > 0; j >>= 1) {
            if (j >= k2) continue;
            if (j >= 32) {
                int rj = j >> 5;
                #pragma unroll
                for (int r = 0; r < 4; ++r) {
                    if ((r & rj) == 0) {
                        int pr = r | rj;
                        bool desc = (((r * 32) & k2) == 0);
                        unsigned long long a = k[r], c2 = k[pr];
                        unsigned long long mx = a > c2 ? a : c2;
                        unsigned long long mn = a > c2 ? c2 : a;
                        k[r]  = desc ? mx : mn;
                        k[pr] = desc ? mn : mx;
                    }
                }
            } else {
                #pragma unroll
                for (int r = 0; r < 4; ++r) {
                    unsigned long long o = __shfl_xor_sync(0xffffffffu, k[r], j);
                    int e = r * 32 + lane;
                    bool takemax = ((e & k2) == 0) == ((lane & j) == 0);
                    bool bigger  = k[r] > o;
                    k[r] = (takemax == bigger) ? k[r] : o;
                }
            }
        }
    }
    if (lane < S)
        g_sorted[((size_t)b * T + t) * S + lane] = k[0];
}

// ============================================================================
// Kernel 2: 4 warps per batch element, pool reg k in warp k, ONE barrier/step,
// packed dual-merge. NEW: payload-packed keys (no divide in decode) and
// reversed-LDS mirror (one fewer shuffle pass in the merge).
// ============================================================================
__global__ __launch_bounds__(128, 1)
void ctc_beam_kernel(const float* __restrict__ data,      // [T, B, C]
                     const int*   __restrict__ data_len,  // [B]
                     float*       __restrict__ out)
{
    const int b    = blockIdx.x;
    const int tid  = threadIdx.x;
    const int lane = tid & 31;
    const int l15  = lane & 15;
    const int wid  = tid >> 5;
    const int len  = data_len[b];
    const unsigned FULL = 0xffffffffu;

    __shared__ unsigned long long s_top[2][4][32];  // [parity][warp][lane]
    __shared__ unsigned short s_bp[T + 1][W];       // row T = scrap (never read)
    __shared__ int   s_selslot[P], s_sellen[P];
    __shared__ float s_selscore[P];

    // staircase map for warps 0-2: slot s = wid*32+lane -> (w, i), i <= 20/(w+1)
    // row counts {21,11,7,6,5,4,3,3,3,3,2,2,2,2,2,2} -> 78 cells; slots 78+ dead
    int pw = -1, pi = 0;
    if (wid < 3) {
        const int pref[17] = {0,21,32,39,45,50,54,57,60,63,66,68,70,72,74,76,78};
        int s = wid * 32 + lane;
        #pragma unroll
        for (int ww = 0; ww < 16; ++ww)
            if (s >= pref[ww] && s < pref[ww + 1]) { pw = ww; pi = s - pref[ww]; }
    }
    const int srt_lane = (lane < S) ? lane : (S - 1);   // clamped always-load

    // row 0 into registers (per warp; lane l holds cols l, l+32, l+64)
    float lp0r, lp1r, lp2r;
    unsigned long long srt_cur;
    {
        const float* row0 = data + (size_t)b * C;
        lp0r = row0[lane]; lp1r = row0[32 + lane]; lp2r = row0[64 + lane];
        srt_cur = g_sorted[((size_t)b * T) * S + srt_lane];
    }

    // replicated register beam state (lane = beam slot; high lanes never read)
    float pb   = (lane == 0) ? 0.0f : NEGF;
    float pnb  = NEGF;
    float ptot = lae(pb, pnb);
    int   llen = 0, llast = -1;

    for (int t = 0; t < len; ++t) {
        // branchless prefetch of row min(t+1, T-1)
        const int tp1 = (t + 1 < T) ? (t + 1) : (T - 1);
        const float* rown = data + (size_t)(tp1 * B + b) * C;
        float n0 = rown[lane], n1 = rown[32 + lane], n2 = rown[64 + lane];
        unsigned long long nsrt = g_sorted[((size_t)b * T + tp1) * S + srt_lane];

        // ---- stay/rep probabilities (every warp; needed for state update)
        float lp_blank = __shfl_sync(FULL, lp0r, 0);
        int ix = (llen > 0) ? llast : 0;
        ix = (ix < 0) ? 0 : ((ix > 95) ? 0 : ix);
        float g0 = __shfl_sync(FULL, lp0r, ix);
        float g1 = __shfl_sync(FULL, lp1r, ix);
        float g2 = __shfl_sync(FULL, lp2r, ix);
        float lpl = (ix < 32) ? g0 : ((ix < 64) ? g1 : g2);
        float spb  = ptot + lp_blank;
        float spnb = (llen > 0) ? (pnb + lpl) : NEGF;

        // ---- pool build: warps 0-2 = staircase ext cells; warp 3 = stay|rep
        unsigned long long k;
        if (wid == 3) {
            unsigned long long staykey =
                pack_key(lae(spb, spnb), lane, 1, lane, 0);
            unsigned long long repkey = (llen > 0)
                ? pack_key(pb + lpl, W + lane * C + llast, 0, lane, llast)
                : 0ULL;
            unsigned long long rk = __shfl_sync(FULL, repkey, l15);
            k = (lane < W) ? staykey : rk;
        } else {
            float pt = __shfl_sync(FULL, ptot,  pw & 15);
            int   lw = __shfl_sync(FULL, llast, pw & 15);
            unsigned long long e = __shfl_sync(FULL, srt_cur, pi);
            int c = 127 - (int)(e & 127ULL);
            unsigned long long key =
                pack_key(funord((unsigned)(e >> 7)) + pt, W + pw * C + c, 0, pw, c);
            k = (pw >= 0 && c != lw) ? key : 0ULL;
        }

        // ---- each warp sorts its own 32 candidates (4 SMSPs in parallel)
        sort32_desc(k, lane);
        s_top[t & 1][wid][lane] = k;        // all 32 lanes: no divergence
        __syncthreads();                    // the ONE barrier per step

        // ---- packed dual-merge with reversed-LDS mirror (9 shuffle passes)
        const int half2 = (lane >> 4) << 1;               // 0 or 2
        unsigned long long a  = s_top[t & 1][half2][l15];
        unsigned long long bm = s_top[t & 1][half2 + 1][15 - l15];  // mirrored load
        unsigned long long v = (a > bm) ? a : bm;
        #pragma unroll
        for (int j = 8; j > 0; j >>= 1) {                 // clean within halves
            unsigned long long o = __shfl_xor_sync(FULL, v, j);
            bool takemax = ((lane & j) == 0);
            bool bigger  = v > o;
            v = (takemax == bigger) ? v : o;
        }
        // final merge: m01 (lanes 0-15) vs m23 (lanes 16-31), mirror = lane^31
        unsigned long long bm2 = __shfl_xor_sync(FULL, v, 31);
        unsigned long long f = (v > bm2) ? v : bm2;
        #pragma unroll
        for (int j = 8; j > 0; j >>= 1) {
            unsigned long long o = __shfl_xor_sync(FULL, f, j);
            bool takemax = ((lane & j) == 0);
            bool bigger  = f > o;
            f = (takemax == bigger) ? f : o;
        }
        // f: lanes 0-15 hold rank-lane winner (lanes 16-31 garbage, never read)

        // ---- state update: payload decode, NO divide
        float score   = key_score(f);
        bool  is_stay = ((f >> 11) & 1ULL) != 0ULL;
        int   parent  = (int)((f >> 7) & 15ULL);
        int   csym    = (int)(f & 127ULL);
        float p_spb  = __shfl_sync(FULL, spb,   parent);
        float p_spnb = __shfl_sync(FULL, spnb,  parent);
        int   p_len  = __shfl_sync(FULL, llen,  parent);
        int   p_last = __shfl_sync(FULL, llast, parent);

        pb    = is_stay ? p_spb  : NEGF;
        pnb   = is_stay ? p_spnb : score;
        ptot  = score;
        llen  = is_stay ? p_len  : (p_len + 1);
        llast = is_stay ? p_last : csym;

        // branchless backpointer store: warp0 lanes 0-15 -> row t, rest -> scrap
        {
            int rowi = (wid == 0 && lane < W) ? t : T;
            s_bp[rowi][l15] =
                (unsigned short)((parent << 8) | (is_stay ? 0xFF : csym));
        }

        // rotate register buffers (warp-private)
        lp0r = n0; lp1r = n1; lp2r = n2; srt_cur = nsrt;
    }

    // ---- final top-P over total beam probabilities (warp 0)
    if (wid == 0) {
        unsigned long long key = (lane < W)
            ? pack_key(ptot, lane, 0, lane, 0) : 0ULL;
        #pragma unroll
        for (int r = 0; r < P; ++r) {
            unsigned long long v = key;
            #pragma unroll
            for (int o = 16; o; o >>= 1) {
                unsigned long long w2 = __shfl_xor_sync(FULL, v, o);
                v = (w2 > v) ? w2 : v;
            }
            if (key == v) key = 0ULL;
            int slot = (int)((v >> 7) & 15ULL);
            int sl = __shfl_sync(FULL, llen, slot);
            if (lane == 0) {
                s_selslot[r]  = slot;
                s_selscore[r] = key_score(v);
                s_sellen[r]   = sl;
            }
        }
    }
    __syncthreads();

    // ---- outputs (flattened float32): -scores, lens, labels
    float* o_neg = out;
    float* o_len = out + B * P;
    float* o_dec = out + 2 * B * P;

    if (tid < P) {
        o_neg[b * P + tid] = -s_selscore[tid];
        o_len[b * P + tid] = (float)s_sellen[tid];
    }
    for (int i = tid; i < P * T; i += 128)
        o_dec[(size_t)b * P * T + i] = -1.0f;
    __syncthreads();

    if (tid < P) {
        int slot = s_selslot[tid];
        int pos  = s_sellen[tid];
        float* dst = o_dec + ((size_t)b * P + tid) * T;
        for (int tt = len - 1; tt >= 0; --tt) {
            unsigned e = s_bp[tt][slot];
            int sym = e & 0xFF;
            slot    = e >> 8;
            if (sym != 0xFF) dst[--pos] = (float)sym;
        }
    }
}

extern "C" void kernel_launch(void* const* d_in, const int* in_sizes, int n_in,
                              void* d_out, int out_size) {
    const float* data = (const float*)d_in[0];
    const int*   dlen = (const int*)d_in[1];
    presort_kernel<<<(B * T + 7) / 8, 256>>>(data);
    ctc_beam_kernel<<<B, 128>>>(data, dlen, (float*)d_out);
}

// round 14
// speedup vs baseline: 1.8982x; 1.1469x over previous
#include <cuda_runtime.h>
#include <stdint.h>

#define NEGF (-1e30f)

constexpr int T = 1024;
constexpr int B = 32;
constexpr int C = 96;
constexpr int W = 16;   // beam width
constexpr int P = 4;    // top paths
constexpr int S = 21;   // top lp columns kept per (b,t); staircase needs i <= 20

// per (b,t): top-S non-blank lp columns as packed keys (ord(lp)<<7 | (127-c)), desc
__device__ unsigned long long g_sorted[(size_t)B * T * S];

// ---------- key helpers ----------
__device__ __forceinline__ unsigned ford(float f) {
    unsigned u = __float_as_uint(f);
    return (u & 0x80000000u) ? ~u : (u | 0x80000000u);
}
__device__ __forceinline__ float funord(unsigned ord) {
    unsigned u = (ord & 0x80000000u) ? (ord ^ 0x80000000u) : ~ord;
    return __uint_as_float(u);
}
// Payload-packed key: [54:23]=ord(score) [22:12]=2047-idx [11]=is_stay
// [10:7]=parent [6:0]=csym.  Order: higher score wins; ties -> lower idx wins
// (matches jax.lax.top_k). Payload bits only compared when (ord,idx) equal,
// which cannot happen for distinct candidates.
__device__ __forceinline__ unsigned long long pack_key(
    float f, int idx, int is_stay, int parent, int csym) {
    return ((unsigned long long)ford(f) << 23)
         | ((unsigned long long)(2047 - idx) << 12)
         | ((unsigned long long)is_stay << 11)
         | ((unsigned long long)parent << 7)
         | (unsigned long long)csym;
}
__device__ __forceinline__ float key_score(unsigned long long k) {
    return funord((unsigned)(k >> 23));
}

__device__ __forceinline__ float lae(float a, float b) {   // jnp.logaddexp
    float m = fmaxf(a, b);
    float d = fabsf(a - b);
    return m + log1pf(expf(-d));
}

// descending bitonic sort of 32 keys across a warp (lane = index)
__device__ __forceinline__ void sort32_desc(unsigned long long& v, int lane) {
    #pragma unroll
    for (int k2 = 2; k2 <= 32; k2 <<= 1) {
        #pragma unroll
        for (int j = k2 >> 1; j > 0; j >>= 1) {
            unsigned long long o = __shfl_xor_sync(0xffffffffu, v, j);
            bool takemax = ((lane & k2) == 0) == ((lane & j) == 0);
            bool bigger  = v > o;
            v = (takemax == bigger) ? v : o;
        }
    }
}

// descending bitonic sort of 16 keys in each half-warp (10 passes; j < 16 so
// all exchanges stay within the half; direction keyed on lane&15)
__device__ __forceinline__ void sort16_desc_halves(unsigned long long& v, int l15) {
    #pragma unroll
    for (int k2 = 2; k2 <= 16; k2 <<= 1) {
        #pragma unroll
        for (int j = k2 >> 1; j > 0; j >>= 1) {
            unsigned long long o = __shfl_xor_sync(0xffffffffu, v, j);
            bool takemax = ((l15 & k2) == 0) == ((l15 & j) == 0);
            bool bigger  = v > o;
            v = (takemax == bigger) ? v : o;
        }
    }
}

// ============================================================================
// Kernel 1: per-(b,t) bitonic sort of non-blank lp columns, keep top-S.
// ============================================================================
__global__ __launch_bounds__(256)
void presort_kernel(const float* __restrict__ data)   // [T, B, C]
{
    int warp = (blockIdx.x * blockDim.x + threadIdx.x) >> 5;
    if (warp >= B * T) return;
    int b = warp / T, t = warp - b * T;
    int lane = threadIdx.x & 31;

    const float* row = data + ((size_t)t * B + b) * C;
    unsigned long long k[4];
    #pragma unroll
    for (int r = 0; r < 4; ++r) {
        int c = r * 32 + lane;
        if (c >= 1 && c < C)
            k[r] = ((unsigned long long)ford(row[c]) << 7) | (unsigned long long)(127 - c);
        else
            k[r] = 0ULL;
    }
    #pragma unroll
    for (int k2 = 2; k2 <= 128; k2 <<= 1) {
        #pragma unroll
        for (int j = 64; j > 0; j >>= 1) {
            if (j >= k2) continue;
            if (j >= 32) {
                int rj = j >> 5;
                #pragma unroll
                for (int r = 0; r < 4; ++r) {
                    if ((r & rj) == 0) {
                        int pr = r | rj;
                        bool desc = (((r * 32) & k2) == 0);
                        unsigned long long a = k[r], c2 = k[pr];
                        unsigned long long mx = a > c2 ? a : c2;
                        unsigned long long mn = a > c2 ? c2 : a;
                        k[r]  = desc ? mx : mn;
                        k[pr] = desc ? mn : mx;
                    }
                }
            } else {
                #pragma unroll
                for (int r = 0; r < 4; ++r) {
                    unsigned long long o = __shfl_xor_sync(0xffffffffu, k[r], j);
                    int e = r * 32 + lane;
                    bool takemax = ((e & k2) == 0) == ((lane & j) == 0);
                    bool bigger  = k[r] > o;
                    k[r] = (takemax == bigger) ? k[r] : o;
                }
            }
        }
    }
    if (lane < S)
        g_sorted[((size_t)b * T + t) * S + lane] = k[0];
}

// ============================================================================
// Kernel 2: 4 warps per batch element, ONE barrier/step, packed dual-merge.
// NEW: in-place demotion (rep candidates folded into the staircase; warp 3
// holds ONLY 16 staykeys -> 10-pass sort16) and spb/spnb computed post-barrier
// (overlaps the merge) in warps 0-2.
// ============================================================================
__global__ __launch_bounds__(128, 1)
void ctc_beam_kernel(const float* __restrict__ data,      // [T, B, C]
                     const int*   __restrict__ data_len,  // [B]
                     float*       __restrict__ out)
{
    const int b    = blockIdx.x;
    const int tid  = threadIdx.x;
    const int lane = tid & 31;
    const int l15  = lane & 15;
    const int wid  = tid >> 5;
    const int len  = data_len[b];
    const unsigned FULL = 0xffffffffu;

    __shared__ unsigned long long s_top[2][4][32];  // [parity][warp][lane]
    __shared__ unsigned short s_bp[T + 1][W];       // row T = scrap (never read)
    __shared__ int   s_selslot[P], s_sellen[P];
    __shared__ float s_selscore[P];

    // staircase map for warps 0-2: slot s = wid*32+lane -> (w, i), i <= 20/(w+1)
    // row counts {21,11,7,6,5,4,3,3,3,3,2,2,2,2,2,2} -> 78 cells; slots 78+ dead
    int pw = -1, pi = 0;
    if (wid < 3) {
        const int pref[17] = {0,21,32,39,45,50,54,57,60,63,66,68,70,72,74,76,78};
        int s = wid * 32 + lane;
        #pragma unroll
        for (int ww = 0; ww < 16; ++ww)
            if (s >= pref[ww] && s < pref[ww + 1]) { pw = ww; pi = s - pref[ww]; }
    }
    const int srt_lane = (lane < S) ? lane : (S - 1);   // clamped always-load

    // row 0 into registers (per warp; lane l holds cols l, l+32, l+64)
    float lp0r, lp1r, lp2r;
    unsigned long long srt_cur;
    {
        const float* row0 = data + (size_t)b * C;
        lp0r = row0[lane]; lp1r = row0[32 + lane]; lp2r = row0[64 + lane];
        srt_cur = g_sorted[((size_t)b * T) * S + srt_lane];
    }

    // replicated register beam state (lane = beam slot; high lanes never read)
    float pb   = (lane == 0) ? 0.0f : NEGF;
    float pnb  = NEGF;
    float ptot = lae(pb, pnb);
    int   llen = 0, llast = -1;

    for (int t = 0; t < len; ++t) {
        // branchless prefetch of row min(t+1, T-1)
        const int tp1 = (t + 1 < T) ? (t + 1) : (T - 1);
        const float* rown = data + (size_t)(tp1 * B + b) * C;
        float n0 = rown[lane], n1 = rown[32 + lane], n2 = rown[64 + lane];
        unsigned long long nsrt = g_sorted[((size_t)b * T + tp1) * S + srt_lane];

        // ---- pool build + per-warp sort
        unsigned long long k;
        if (wid == 3) {
            // warp 3: ONLY the 16 stay candidates (needs the lae)
            float lp_blank = __shfl_sync(FULL, lp0r, 0);
            int ix = (llen > 0) ? llast : 0;
            ix = (ix < 0) ? 0 : ((ix > 95) ? 0 : ix);
            float g0 = __shfl_sync(FULL, lp0r, ix);
            float g1 = __shfl_sync(FULL, lp1r, ix);
            float g2 = __shfl_sync(FULL, lp2r, ix);
            float lpl = (ix < 32) ? g0 : ((ix < 64) ? g1 : g2);
            float spb3  = ptot + lp_blank;
            float spnb3 = (llen > 0) ? (pnb + lpl) : NEGF;
            unsigned long long staykey =
                pack_key(lae(spb3, spnb3), lane, 1, lane, 0);
            k = (lane < W) ? staykey : 0ULL;
            sort16_desc_halves(k, l15);      // 10 passes; lanes 0-15 sorted desc
        } else {
            // warps 0-2: staircase ext cells with IN-PLACE demotion
            float pt  = __shfl_sync(FULL, ptot,  pw & 15);
            float pbw = __shfl_sync(FULL, pb,    pw & 15);
            int   lw  = __shfl_sync(FULL, llast, pw & 15);
            unsigned long long e = __shfl_sync(FULL, srt_cur, pi);
            int c = 127 - (int)(e & 127ULL);
            float base = (c == lw) ? pbw : pt;   // demoted cell = rep candidate
            unsigned long long key =
                pack_key(funord((unsigned)(e >> 7)) + base, W + pw * C + c, 0, pw, c);
            k = (pw >= 0) ? key : 0ULL;
            sort32_desc(k, lane);                // 15 passes
        }
        s_top[t & 1][wid][lane] = k;             // all 32 lanes: no divergence
        __syncthreads();                         // the ONE barrier per step

        // ---- stay/rep probabilities for the update (overlaps merge below)
        float lp_blank = __shfl_sync(FULL, lp0r, 0);
        int ix = (llen > 0) ? llast : 0;
        ix = (ix < 0) ? 0 : ((ix > 95) ? 0 : ix);
        float g0 = __shfl_sync(FULL, lp0r, ix);
        float g1 = __shfl_sync(FULL, lp1r, ix);
        float g2 = __shfl_sync(FULL, lp2r, ix);
        float lpl = (ix < 32) ? g0 : ((ix < 64) ? g1 : g2);
        float spb  = ptot + lp_blank;
        float spnb = (llen > 0) ? (pnb + lpl) : NEGF;

        // ---- packed dual-merge with reversed-LDS mirror (9 shuffle passes)
        const int half2 = (lane >> 4) << 1;               // 0 or 2
        unsigned long long a  = s_top[t & 1][half2][l15];
        unsigned long long bm = s_top[t & 1][half2 + 1][15 - l15];  // mirrored load
        unsigned long long v = (a > bm) ? a : bm;
        #pragma unroll
        for (int j = 8; j > 0; j >>= 1) {                 // clean within halves
            unsigned long long o = __shfl_xor_sync(FULL, v, j);
            bool takemax = ((lane & j) == 0);
            bool bigger  = v > o;
            v = (takemax == bigger) ? v : o;
        }
        // final merge: m01 (lanes 0-15) vs m23 (lanes 16-31), mirror = lane^31
        unsigned long long bm2 = __shfl_xor_sync(FULL, v, 31);
        unsigned long long f = (v > bm2) ? v : bm2;
        #pragma unroll
        for (int j = 8; j > 0; j >>= 1) {
            unsigned long long o = __shfl_xor_sync(FULL, f, j);
            bool takemax = ((lane & j) == 0);
            bool bigger  = f > o;
            f = (takemax == bigger) ? f : o;
        }
        // f: lanes 0-15 hold rank-lane winner (lanes 16-31 garbage, never read)

        // ---- state update: payload decode, NO divide
        float score   = key_score(f);
        bool  is_stay = ((f >> 11) & 1ULL) != 0ULL;
        int   parent  = (int)((f >> 7) & 15ULL);
        int   csym    = (int)(f & 127ULL);
        float p_spb  = __shfl_sync(FULL, spb,   parent);
        float p_spnb = __shfl_sync(FULL, spnb,  parent);
        int   p_len  = __shfl_sync(FULL, llen,  parent);
        int   p_last = __shfl_sync(FULL, llast, parent);

        pb    = is_stay ? p_spb  : NEGF;
        pnb   = is_stay ? p_spnb : score;
        ptot  = score;
        llen  = is_stay ? p_len  : (p_len + 1);
        llast = is_stay ? p_last : csym;

        // branchless backpointer store: warp0 lanes 0-15 -> row t, rest -> scrap
        {
            int rowi = (wid == 0 && lane < W) ? t : T;
            s_bp[rowi][l15] =
                (unsigned short)((parent << 8) | (is_stay ? 0xFF : csym));
        }

        // rotate register buffers (warp-private)
        lp0r = n0; lp1r = n1; lp2r = n2; srt_cur = nsrt;
    }

    // ---- final top-P over total beam probabilities (warp 0)
    if (wid == 0) {
        unsigned long long key = (lane < W)
            ? pack_key(ptot, lane, 0, lane, 0) : 0ULL;
        #pragma unroll
        for (int r = 0; r < P; ++r) {
            unsigned long long v = key;
            #pragma unroll
            for (int o = 16; o; o >>= 1) {
                unsigned long long w2 = __shfl_xor_sync(FULL, v, o);
                v = (w2 > v) ? w2 : v;
            }
            if (key == v) key = 0ULL;
            int slot = (int)((v >> 7) & 15ULL);
            int sl = __shfl_sync(FULL, llen, slot);
            if (lane == 0) {
                s_selslot[r]  = slot;
                s_selscore[r] = key_score(v);
                s_sellen[r]   = sl;
            }
        }
    }
    __syncthreads();

    // ---- outputs (flattened float32): -scores, lens, labels
    float* o_neg = out;
    float* o_len = out + B * P;
    float* o_dec = out + 2 * B * P;

    if (tid < P) {
        o_neg[b * P + tid] = -s_selscore[tid];
        o_len[b * P + tid] = (float)s_sellen[tid];
    }
    for (int i = tid; i < P * T; i += 128)
        o_dec[(size_t)b * P * T + i] = -1.0f;
    __syncthreads();

    if (tid < P) {
        int slot = s_selslot[tid];
        int pos  = s_sellen[tid];
        float* dst = o_dec + ((size_t)b * P + tid) * T;
        for (int tt = len - 1; tt >= 0; --tt) {
            unsigned e = s_bp[tt][slot];
            int sym = e & 0xFF;
            slot    = e >> 8;
            if (sym != 0xFF) dst[--pos] = (float)sym;
        }
    }
}

extern "C" void kernel_launch(void* const* d_in, const int* in_sizes, int n_in,
                              void* d_out, int out_size) {
    const float* data = (const float*)d_in[0];
    const int*   dlen = (const int*)d_in[1];
    presort_kernel<<<(B * T + 7) / 8, 256>>>(data);
    ctc_beam_kernel<<<B, 128>>>(data, dlen, (float*)d_out);
}